// round 2
// baseline (speedup 1.0000x reference)
#include <cuda_runtime.h>

// Problem constants
#define B 256
#define N_IN 100          // input retrieval dim
#define R 80              // RETRIEVAL_NUM
#define D 768             // feature dim
#define THRESH 0.5f

// Output layout (flattened concatenation, all float32):
//   vis_packed : B*R*D            at offset 0
//   txt_packed : B*R*D            at offset B*R*D
//   text_mask  : B*(R+1)          next
//   img_mask   : B*(R+1)          next
//   rr_mod     : B*R              next
//   labels     : B*R              next
#define OFF_VIS   0
#define OFF_TXT   ((size_t)B * R * D)
#define OFF_TMASK ((size_t)2 * B * R * D)
#define OFF_IMASK (OFF_TMASK + (size_t)B * (R + 1))
#define OFF_RRMOD (OFF_IMASK + (size_t)B * (R + 1))
#define OFF_LBL   (OFF_RRMOD + (size_t)B * R)

// Scratch (device globals: allocation-free)
__device__ int g_idx[B * R];
__device__ int g_cnt[B];

// ---------------------------------------------------------------------------
// Kernel 1: per-batch-row metadata + small outputs.
// grid = B, block = 128
// ---------------------------------------------------------------------------
__global__ void build_meta(const float* __restrict__ rrcp,
                           const float* __restrict__ labels_in,
                           float* __restrict__ out) {
    __shared__ float sh_r[R];
    __shared__ int sh_cnt;
    __shared__ int sh_all_below;   // 1 if all rr < 0.5 (zero_rows)

    const int b = blockIdx.x;
    const int t = threadIdx.x;

    if (t < R) sh_r[t] = rrcp[b * N_IN + t];
    __syncthreads();

    if (t == 0) {
        int cnt = 0;
        int all_below = 1;
        #pragma unroll 4
        for (int i = 0; i < R; ++i) {
            float r = sh_r[i];
            if (r > THRESH) {               // binary = 1 (strict >)
                g_idx[b * R + cnt] = i;
                ++cnt;
            }
            if (r >= THRESH) all_below = 0; // rr_mod nonzero iff rr >= 0.5
        }
        g_cnt[b] = cnt;
        sh_cnt = cnt;
        sh_all_below = all_below;
    }
    __syncthreads();

    const int cnt = sh_cnt;

    // rr_mod + labels
    if (t < R) {
        float r = sh_r[t];
        float rm = (r < THRESH) ? 0.0f : r;
        if (t == 0 && sh_all_below) rm = 1.0f;
        out[OFF_RRMOD + (size_t)b * R + t] = rm;
        out[OFF_LBL   + (size_t)b * R + t] = labels_in[b * N_IN + t];
    }

    // masks (R+1 = 81 entries)
    if (t < R + 1) {
        float tm = (t <= cnt) ? 1.0f : 0.0f;
        out[OFF_TMASK + (size_t)b * (R + 1) + t] = tm;
        float im = (b == B - 1) ? tm : 1.0f;
        out[OFF_IMASK + (size_t)b * (R + 1) + t] = im;
    }
}

// ---------------------------------------------------------------------------
// Kernel 2: big gather. One block per (b, j, which) row of 768 floats.
// grid = (B*R, 2), block = 192  (one float4 per thread, 3072B coalesced)
// ---------------------------------------------------------------------------
__global__ void __launch_bounds__(192)
gather_rows(const float* __restrict__ vis,
            const float* __restrict__ txt,
            float* __restrict__ out) {
    const int job = blockIdx.x;          // b*R + j
    const int b = job / R;
    const int j = job - b * R;
    const int which = blockIdx.y;        // 0 = vis, 1 = txt

    float4* dst = reinterpret_cast<float4*>(
        out + (which ? OFF_TXT : OFF_VIS) + (size_t)job * D) + threadIdx.x;

    const int cnt = g_cnt[b];
    if (j < cnt) {
        const int src = g_idx[job];
        const float* s_base = (which ? txt : vis) + ((size_t)b * N_IN + src) * D;
        *dst = *(reinterpret_cast<const float4*>(s_base) + threadIdx.x);
    } else {
        *dst = make_float4(0.0f, 0.0f, 0.0f, 0.0f);
    }
}

// ---------------------------------------------------------------------------
extern "C" void kernel_launch(void* const* d_in, const int* in_sizes, int n_in,
                              void* d_out, int out_size) {
    // Input order per metadata:
    // 0: mean_pooling_vec (unused)
    // 1: merge_text_vec (unused)
    // 2: retrieved_visual_feature_embedding_cls (B,N,1,D)
    // 3: retrieved_textual_feature_embedding   (B,N,1,D)
    // 4: retrieved_label_list (B,N)
    // 5: RRCP (B,N)
    const float* vis    = (const float*)d_in[2];
    const float* txt    = (const float*)d_in[3];
    const float* labels = (const float*)d_in[4];
    const float* rrcp   = (const float*)d_in[5];
    float* out = (float*)d_out;

    build_meta<<<B, 128>>>(rrcp, labels, out);
    gather_rows<<<dim3(B * R, 2), 192>>>(vis, txt, out);
}